// round 13
// baseline (speedup 1.0000x reference)
#include <cuda_runtime.h>
#include <cuda_bf16.h>

// Problem constants
#define BB 128
#define FHH 26
#define FWW 26
#define TT 50
#define AA 5
#define NCLS 20
#define KK (FHH*FWW)          // 676
#define KA (KK*AA)            // 3380
#define CH (5+NCLS)           // 25
#define OBJ_SCALE 5.0f

#define THR 1024
#define NWARP 32              // 30 streaming + 2 assignment
#define NSW 30                // streaming warps (6 per anchor type)
#define WPA 6                 // warps per anchor type
#define WPC 113               // cells per warp (6*113 = 678 >= 676)
#define NA 4                  // slots per lane (32*4 = 128 >= 113)
#define SQ7 2.6457513110645906f

__constant__ float c_aw[AA] = {1.3221f, 3.19275f, 5.05587f, 9.47112f, 11.2364f};
__constant__ float c_ah[AA] = {1.73145f, 4.00944f, 8.09892f, 4.84053f, 10.0071f};

// Scratch
__device__ float    g_loss[BB];
__device__ unsigned g_done = 0;

__device__ __forceinline__ float sigmoidf_(float x) {
    return 1.0f / (1.0f + __expf(-x));
}

// Full decode for the assignment path — expression-identical to the
// streaming phase1+phase2 sequence.
__device__ __forceinline__ void decode_core(
    const float* __restrict__ p, int a, int xx, int yy,
    float& nx1, float& ny1, float& px2, float& py2,
    float& pa3, float& conf, float& sx, float& sy,
    float& ew, float& eh, float& pa7)
{
    float tx = p[0], ty = p[KK], tw = p[2*KK], th = p[3*KK], tc = p[4*KK];
    sx = sigmoidf_(tx); sy = sigmoidf_(ty);
    ew = __expf(tw);    eh = __expf(th);
    conf = sigmoidf_(tc);
    float pw = c_aw[a] * ew, ph = c_ah[a] * eh;
    float pa = pw * ph;
    pa3 = 3.0f * pa;
    float pcx = (float)xx + sx, pcy = (float)yy + sy;
    float pwS = SQ7 * pw, phS = SQ7 * ph;
    float px1 = fmaf(SQ7, pcx, -0.5f * pwS);
    px2       = fmaf(SQ7, pcx,  0.5f * pwS);
    float py1 = fmaf(SQ7, pcy, -0.5f * phS);
    py2       = fmaf(SQ7, pcy,  0.5f * phS);
    nx1 = -px1; ny1 = -py1;
    pa7 = pwS * phS;
}

// ---------------------------------------------------------------------------
// ONE block per batch (grid = 128, 1024 threads = 32 warps):
//   warps 0..29  : streaming — warp w covers anchor a = w/6, cells
//                  [(w%6)*113, ...+113) of the 26x26 grid.
//   warps 30..31 : assignment + assigned-anchor losses + corrections.
// gt prolog paid ONCE per batch; per-batch loss (incl. pos_any) computed
// in-block; last block sums 128 scalars.
// ---------------------------------------------------------------------------
__global__ __launch_bounds__(THR)
void mainKernel(const float* __restrict__ outputs,
                const float* __restrict__ targets,
                float* __restrict__ out) {
    const int b   = blockIdx.x;
    const int tid = threadIdx.x;
    const int wid = tid >> 5;
    const int lid = tid & 31;

    __shared__ float4 s_gt[TT];          // scaled (X1,Y1,X2,Y2), sanitized
    __shared__ float  s_mg4[TT];         // -12 * unscaled gt area
    __shared__ float  s_ga7[TT];         // 7 * unscaled gt area
    // warp-private compact lists (+2 sentinel slots each)
    __shared__ float4 s_cw[NSW][TT+2];   // (X2, Y2, -X1, -Y1)
    __shared__ float  s_cm[NSW][TT+2];   // -12*ga
    // assignment data
    __shared__ int    s_slot[TT];
    __shared__ int    s_valid[TT];
    __shared__ float4 s_tb[TT];
    __shared__ int    s_cls[TT];

    // ---- gt decode + assignment prolog (once per batch) ----
    if (tid < TT) {
        const float* g = targets + ((size_t)b * TT + tid) * 5;
        float x1 = g[0], y1 = g[1], x2 = g[2], y2 = g[3], cl = g[4];
        bool valid = (x1 + y1 + x2 + y2) > 0.0f;

        float gx1 = x1 * FWW, gy1 = y1 * FHH, gx2 = x2 * FWW, gy2 = y2 * FHH;
        float gw = gx2 - gx1, gh = gy2 - gy1;
        float ga = gw * gh;

        if (valid) {
            s_gt[tid] = make_float4(SQ7*gx1, SQ7*gy1, SQ7*gx2, SQ7*gy2);
            s_mg4[tid] = 4.0f * (-3.0f * ga);
            s_ga7[tid] = 7.0f * ga;
        } else {
            s_gt[tid] = make_float4(1e8f, 1e8f, 1e8f, 1e8f);
            s_mg4[tid] = 0.0f;   // ga12 = 0 -> always culled by area test
            s_ga7[tid] = 0.0f;
        }

        {
            float gcx = 0.5f * (gx1 + gx2), gcy = 0.5f * (gy1 + gy2);
            int cx = min(max((int)floorf(gcx), 0), FWW - 1);
            int cy = min(max((int)floorf(gcy), 0), FHH - 1);
            int cell = cy * FWW + cx;

            float acx = (float)cx + 0.5f, acy = (float)cy + 0.5f;
            float best = -1e30f;
            int aidx = 0;
            #pragma unroll
            for (int a = 0; a < AA; a++) {
                float aw = c_aw[a], ah = c_ah[a];
                float ax1 = acx - 0.5f*aw, ax2 = acx + 0.5f*aw;
                float ay1 = acy - 0.5f*ah, ay2 = acy + 0.5f*ah;
                float xi1 = fmaxf(ax1, gx1), yi1 = fmaxf(ay1, gy1);
                float xi2 = fminf(ax2, gx2), yi2 = fminf(ay2, gy2);
                float inter = fmaxf(xi2 - xi1, 0.0f) * fmaxf(yi2 - yi1, 0.0f);
                float iou = inter / (aw * ah + ga - inter);
                if (iou > best) { best = iou; aidx = a; }
            }
            s_tb[tid]   = make_float4(gcx - (float)cx, gcy - (float)cy,
                                      gw / c_aw[aidx], gh / c_ah[aidx]);
            s_cls[tid]  = (int)cl;
            s_slot[tid] = cell * AA + aidx;
            s_valid[tid] = valid ? 1 : 0;
        }
    }
    __syncthreads();   // the ONLY block sync before the final reduction

    const float* ob = outputs + (size_t)b * CH * KA;

    float r0 = 0.0f, r1 = 0.0f, r2 = 0.0f, r3 = 0.0f;

    if (wid < NSW) {
        // -------------------- streaming warp --------------------
        const int a = wid / WPA;
        const int wbase = (wid % WPA) * WPC;    // contiguous 113-cell range
        const float* pbase = ob + (size_t)(a * CH) * KK;

        // ---- phase 1: load tw/th/tc; conservative geometry (warp-local) ----
        int   kc[NA];
        bool  v[NA];
        float pw[NA], ph[NA], pa12[NA], c2[NA];
        float cxlo = 1e30f, cylo = 1e30f, cxhi = -1e30f, cyhi = -1e30f;
        float pmn = 1e30f, pmx = -1e30f;
        #pragma unroll
        for (int j = 0; j < NA; j++) {
            int sl = lid + j * 32;
            int k = wbase + sl;
            v[j] = (sl < WPC) && (k < KK);
            if (!v[j]) k = wbase;
            kc[j] = k;
            int yy = k / FWW, xx = k - yy * FWW;
            const float* p = pbase + k;
            float tw = p[2*KK], th = p[3*KK], tc = p[4*KK];
            float ew = __expf(tw), eh = __expf(th);
            float conf = sigmoidf_(tc);
            pw[j] = c_aw[a] * ew;
            ph[j] = c_ah[a] * eh;
            float pa = pw[j] * ph[j];
            pa12[j] = 4.0f * (3.0f * pa);
            c2[j] = conf * conf;
            // conservative corners: center in (xx, xx+1) x (yy, yy+1)
            cxlo = fminf(cxlo, SQ7 * ((float)xx       - 0.5f * pw[j]));
            cxhi = fmaxf(cxhi, SQ7 * ((float)(xx + 1) + 0.5f * pw[j]));
            cylo = fminf(cylo, SQ7 * ((float)yy       - 0.5f * ph[j]));
            cyhi = fmaxf(cyhi, SQ7 * ((float)(yy + 1) + 0.5f * ph[j]));
            pmn = fminf(pmn, pa12[j]);
            pmx = fmaxf(pmx, pa12[j]);
        }

        // warp-level butterfly reduce (all lanes get results; no smem/sync)
        #pragma unroll
        for (int o = 16; o > 0; o >>= 1) {
            cxlo = fminf(cxlo, __shfl_xor_sync(0xffffffffu, cxlo, o));
            cylo = fminf(cylo, __shfl_xor_sync(0xffffffffu, cylo, o));
            cxhi = fmaxf(cxhi, __shfl_xor_sync(0xffffffffu, cxhi, o));
            cyhi = fmaxf(cyhi, __shfl_xor_sync(0xffffffffu, cyhi, o));
            pmn  = fminf(pmn,  __shfl_xor_sync(0xffffffffu, pmn,  o));
            pmx  = fmaxf(pmx,  __shfl_xor_sync(0xffffffffu, pmx,  o));
        }

        // warp-private cull via ballot compaction (deterministic, no sync).
        // IoU >= 0.75 requires ga in [0.75pa, 4/3 pa] -> keep iff
        // 12ga in [0.749*pmn, 1.335*pmx]; plus conservative bbox overlap.
        // Culled gts provably can't reach the threshold -> flags exact.
        const float loA = 0.749f * pmn, hiA = 1.335f * pmx;
        const unsigned ltmask = (1u << lid) - 1u;
        int wcnt = 0;
        {
            // round 1: t = lid (0..31)
            float4 g = s_gt[lid];
            float ga12 = -s_mg4[lid];
            bool pred = (g.x < cxhi && g.z > cxlo && g.y < cyhi && g.w > cylo &&
                         ga12 >= loA && ga12 <= hiA);
            unsigned m = __ballot_sync(0xffffffffu, pred);
            if (pred) {
                int pos = __popc(m & ltmask);
                s_cw[wid][pos] = make_float4(g.z, g.w, -g.x, -g.y);
                s_cm[wid][pos] = s_mg4[lid];
            }
            wcnt = __popc(m);
            // round 2: t = 32 + lid (32..49)
            int t2 = 32 + lid;
            bool in2 = t2 < TT;
            float4 g2 = in2 ? s_gt[t2] : make_float4(1e8f,1e8f,1e8f,1e8f);
            float ga2 = in2 ? -s_mg4[t2] : 0.0f;
            bool pred2 = in2 && (g2.x < cxhi && g2.z > cxlo &&
                                 g2.y < cyhi && g2.w > cylo &&
                                 ga2 >= loA && ga2 <= hiA);
            unsigned m2 = __ballot_sync(0xffffffffu, pred2);
            if (pred2) {
                int pos = wcnt + __popc(m2 & ltmask);
                s_cw[wid][pos] = make_float4(g2.z, g2.w, -g2.x, -g2.y);
                s_cm[wid][pos] = s_mg4[t2];
            }
            wcnt += __popc(m2);
        }
        // sentinels (exact no-ops: u=v=0, mg=0 -> f=0 <= acc)
        if (lid < 2) {
            s_cw[wid][wcnt + lid] = make_float4(-1e8f, -1e8f, -1e8f, -1e8f);
            s_cm[wid][wcnt + lid] = 0.0f;
        }
        __syncwarp();

        float acc4[NA];
        #pragma unroll
        for (int j = 0; j < NA; j++) acc4[j] = 0.0f;

        if (wcnt > 0) {  // warp-uniform: skip phase 2 + loop entirely
            // ---- phase 2: load tx/ty, exact corners ----
            float nx1[NA], ny1[NA], px2[NA], py2[NA];
            #pragma unroll
            for (int j = 0; j < NA; j++) {
                const float* p = pbase + kc[j];
                float tx = p[0], ty = p[KK];
                float sx = sigmoidf_(tx), sy = sigmoidf_(ty);
                int yy = kc[j] / FWW, xx = kc[j] - yy * FWW;
                float pcx = (float)xx + sx, pcy = (float)yy + sy;
                float pwS = SQ7 * pw[j], phS = SQ7 * ph[j];
                float px1 = fmaf(SQ7, pcx, -0.5f * pwS);
                px2[j]    = fmaf(SQ7, pcx,  0.5f * pwS);
                float py1 = fmaf(SQ7, pcy, -0.5f * phS);
                py2[j]    = fmaf(SQ7, pcy,  0.5f * phS);
                nx1[j] = -px1; ny1[j] = -py1;
            }

            const float4* cw = s_cw[wid];
            const float*  cm = s_cm[wid];
            const int cntUp = (wcnt + 1) & ~1;
            for (int i = 0; i < cntUp; i += 2) {
                float4 cA = cw[i],   cB = cw[i+1];
                float mgA = cm[i],   mgB = cm[i+1];
                #pragma unroll
                for (int j = 0; j < NA; j++) {
                    float dxA = fminf(px2[j], cA.x) + fminf(nx1[j], cA.z);
                    float dyA = fminf(py2[j], cA.y) + fminf(ny1[j], cA.w);
                    float uA = dxA + fabsf(dxA);   // = 2*max(dxA,0) exactly
                    float vA = dyA + fabsf(dyA);
                    acc4[j] = fmaxf(acc4[j], fmaf(uA, vA, mgA));
                }
                #pragma unroll
                for (int j = 0; j < NA; j++) {
                    float dxB = fminf(px2[j], cB.x) + fminf(nx1[j], cB.z);
                    float dyB = fminf(py2[j], cB.y) + fminf(ny1[j], cB.w);
                    float uB = dxB + fabsf(dxB);
                    float vB = dyB + fabsf(dyB);
                    acc4[j] = fmaxf(acc4[j], fmaf(uB, vB, mgB));
                }
            }
        }

        float posAny = 0.0f;
        #pragma unroll
        for (int j = 0; j < NA; j++) {
            if (v[j]) {
                r0 += c2[j];
                if (acc4[j] >= pa12[j]) r1 += c2[j];
                if (acc4[j] >  pa12[j]) posAny = 1.0f;
            }
        }
        r3 = posAny;
    } else {
        // -------------------- assignment warps (wid 30, 31) ------------------
        int t = (wid - NSW) * 32 + lid;
        if (t < TT) {
            // dedup locally: keep t only if no LATER valid t' hits same slot
            int slot = s_slot[t];
            bool fin = (s_valid[t] != 0);
            if (fin) {
                for (int t2 = t + 1; t2 < TT; t2++)
                    if (s_valid[t2] && s_slot[t2] == slot) { fin = false; break; }
            }

            if (fin) {
                int k = slot / AA, a = slot - k * AA;
                int yy = k / FWW, xx = k - yy * FWW;
                const float* p = ob + (size_t)(a * CH) * KK + k;

                float nx1, ny1, px2, py2, pa3, conf, sx, sy, ew, eh, pa7;
                decode_core(p, a, xx, yy, nx1, ny1, px2, py2, pa3,
                            conf, sx, sy, ew, eh, pa7);
                float pa12 = 4.0f * pa3;

                // exact max-IoU over ALL gts + SAME flag expression
                float bi = 0.0f, bd = 1.0f, acc4 = 0.0f;
                for (int tt2 = 0; tt2 < TT; tt2++) {
                    float4 g = s_gt[tt2];
                    float dx = fminf(px2, g.z) + fminf(nx1, -g.x);
                    float dy = fminf(py2, g.w) + fminf(ny1, -g.y);
                    float u = dx + fabsf(dx);
                    float vv = dy + fabsf(dy);
                    acc4 = fmaxf(acc4, fmaf(u, vv, s_mg4[tt2]));
                    float ix = 0.5f * u;                 // = max(dx,0) exactly
                    float iy = 0.5f * vv;
                    float inter = ix * iy;               // scaled (=7*inter)
                    float den = pa7 + s_ga7[tt2] - inter;
                    bool win = (inter * bd > bi * den);
                    bi = win ? inter : bi;
                    bd = win ? den : bd;
                }
                float miou = bi / bd;

                float4 tb = s_tb[t];
                float d0 = sx - tb.x, d1 = sy - tb.y;
                float d2 = ew - tb.z, d3 = eh - tb.w;
                float asg = 0.5f * (d0*d0 + d1*d1 + d2*d2 + d3*d3);
                float di = OBJ_SCALE * conf - OBJ_SCALE * miou;
                asg += 0.5f * di * di;
                float lmax = -1e30f;
                #pragma unroll
                for (int c = 0; c < NCLS; c++) lmax = fmaxf(lmax, p[(5 + c) * KK]);
                float se = 0.0f;
                #pragma unroll
                for (int c = 0; c < NCLS; c++) se += __expf(p[(5 + c) * KK] - lmax);
                asg += (lmax + __logf(se)) - p[(5 + s_cls[t]) * KK];

                r2 = asg;
                float cc = conf * conf;
                r0 = -cc;                    // correction: remove noobj term
                if (acc4 >= pa12) r1 = -cc;  // correction: remove flag term
            }
        }
    }

    // ---- block reduction over 32 warps (deterministic) ----
    #pragma unroll
    for (int o = 16; o > 0; o >>= 1) {
        r0 += __shfl_down_sync(0xffffffffu, r0, o);
        r1 += __shfl_down_sync(0xffffffffu, r1, o);
        r2 += __shfl_down_sync(0xffffffffu, r2, o);
        r3 += __shfl_down_sync(0xffffffffu, r3, o);
    }
    __shared__ float rA[NWARP], rBs[NWARP], rG[NWARP], rP[NWARP];
    if (lid == 0) { rA[wid] = r0; rBs[wid] = r1; rG[wid] = r2; rP[wid] = r3; }
    __syncthreads();

    __shared__ int s_last;
    if (tid == 0) {
        float sA = 0, sB = 0, sG = 0, sP = 0;
        #pragma unroll
        for (int i = 0; i < NWARP; i++) {
            sA += rA[i]; sB += rBs[i]; sG += rG[i]; sP += rP[i];
        }
        bool pos = sP > 0.0f;
        g_loss[b] = 0.5f * (sA - (pos ? sB : 0.0f)) + sG;
        __threadfence();
        unsigned done = atomicAdd(&g_done, 1u);
        s_last = (done == (unsigned)(BB - 1)) ? 1 : 0;
    }
    __syncthreads();

    // ---- last block: sum 128 per-batch losses (deterministic) ----
    if (s_last) {
        __shared__ float red[BB];
        if (tid < BB) red[tid] = g_loss[tid];
        __syncthreads();
        #pragma unroll
        for (int s = BB / 2; s > 0; s >>= 1) {
            if (tid < s) red[tid] += red[tid + s];
            __syncthreads();
        }
        if (tid == 0) {
            out[0] = red[0] / (float)BB;
            g_done = 0;  // reset for next graph replay
        }
    }
}

// ---------------------------------------------------------------------------
extern "C" void kernel_launch(void* const* d_in, const int* in_sizes, int n_in,
                              void* d_out, int out_size) {
    const float* outputs = (const float*)d_in[0];
    const float* targets = (const float*)d_in[1];
    if (n_in >= 2 && in_sizes[0] < in_sizes[1]) {
        outputs = (const float*)d_in[1];
        targets = (const float*)d_in[0];
    }
    float* out = (float*)d_out;

    mainKernel<<<BB, THR>>>(outputs, targets, out);
}

// round 14
// speedup vs baseline: 3.5369x; 3.5369x over previous
#include <cuda_runtime.h>
#include <cuda_bf16.h>

// Problem constants
#define BB 128
#define FHH 26
#define FWW 26
#define TT 50
#define AA 5
#define NCLS 20
#define KK (FHH*FWW)          // 676
#define KA (KK*AA)            // 3380
#define CH (5+NCLS)           // 25
#define OBJ_SCALE 5.0f

#define SPARTS AA             // 5 streaming parts (one per anchor type)
#define NPARTS (SPARTS + 1)   // + assignment part
#define THR 192
#define NW (THR/32)           // 6 warps
#define WPC 113               // cells per warp (6*113 = 678 >= 676)
#define NA 4                  // slots per lane (32*4 = 128 >= 113)
#define SQ7 2.6457513110645906f

__constant__ float c_aw[AA] = {1.3221f, 3.19275f, 5.05587f, 9.47112f, 11.2364f};
__constant__ float c_ah[AA] = {1.73145f, 4.00944f, 8.09892f, 4.84053f, 10.0071f};

// Scratch
__device__ float4 g_part[BB][NPARTS];
__device__ unsigned g_done = 0;

__device__ __forceinline__ float sigmoidf_(float x) {
    return 1.0f / (1.0f + __expf(-x));
}

// Full decode for the assignment path — expression-identical to the
// streaming phase1+phase2 sequence.
__device__ __forceinline__ void decode_core(
    const float* __restrict__ p, int a, int xx, int yy,
    float& nx1, float& ny1, float& px2, float& py2,
    float& pa3, float& conf, float& sx, float& sy,
    float& ew, float& eh, float& pa7)
{
    float tx = p[0], ty = p[KK], tw = p[2*KK], th = p[3*KK], tc = p[4*KK];
    sx = sigmoidf_(tx); sy = sigmoidf_(ty);
    ew = __expf(tw);    eh = __expf(th);
    conf = sigmoidf_(tc);
    float pw = c_aw[a] * ew, ph = c_ah[a] * eh;
    float pa = pw * ph;
    pa3 = 3.0f * pa;
    float pcx = (float)xx + sx, pcy = (float)yy + sy;
    float pwS = SQ7 * pw, phS = SQ7 * ph;
    float px1 = fmaf(SQ7, pcx, -0.5f * pwS);
    px2       = fmaf(SQ7, pcx,  0.5f * pwS);
    float py1 = fmaf(SQ7, pcy, -0.5f * phS);
    py2       = fmaf(SQ7, pcy,  0.5f * phS);
    nx1 = -px1; ny1 = -py1;
    pa7 = pwS * phS;
}

// ---------------------------------------------------------------------------
// grid (B, 6): part < 5 -> streaming over all 676 cells of anchor `part`
// (6 warps x 113 contiguous cells each); part 5 -> assignment.
// All anchor-channel LDGs (incl. tx/ty) are issued BEFORE the gt decode so
// every DRAM latency overlaps in one MLP window; one __syncthreads total
// before the final reduction; culling is warp-private (shfl + ballot).
// ---------------------------------------------------------------------------
__global__ __launch_bounds__(THR)
void mainKernel(const float* __restrict__ outputs,
                const float* __restrict__ targets,
                float* __restrict__ out) {
    const int b    = blockIdx.x;
    const int part = blockIdx.y;
    const int tid  = threadIdx.x;
    const int wid  = tid >> 5;
    const int lid  = tid & 31;

    __shared__ float4 s_gt[TT];          // scaled (X1,Y1,X2,Y2), sanitized
    __shared__ float  s_mg4[TT];         // -12 * unscaled gt area
    __shared__ float  s_ga7[TT];         // 7 * unscaled gt area (assignment)
    // warp-private compact lists (+2 sentinel slots each)
    __shared__ float4 s_cw[NW][TT+2];    // (X2, Y2, -X1, -Y1)
    __shared__ float  s_cm[NW][TT+2];    // -12*ga
    // assignment-only
    __shared__ int    s_slot[TT];
    __shared__ int    s_valid[TT];
    __shared__ float4 s_tb[TT];
    __shared__ int    s_cls[TT];

    const float* ob = outputs + (size_t)b * CH * KA;

    // ================= phase 1 (streaming blocks): issue ALL anchor loads
    // and gt-independent decode BEFORE the gt prolog/sync =================
    int   kc[NA];
    bool  v[NA];
    float pw[NA], ph[NA], pa12[NA], c2[NA], txr[NA], tyr[NA];
    float cxlo = 1e30f, cylo = 1e30f, cxhi = -1e30f, cyhi = -1e30f;
    float pmn = 1e30f, pmx = -1e30f;
    const int a = part;                  // anchor type (streaming only)
    if (part < SPARTS) {
        const float* pbase = ob + (size_t)(a * CH) * KK;
        const int wbase = wid * WPC;     // warp-contiguous 113-cell range
        #pragma unroll
        for (int j = 0; j < NA; j++) {
            int sl = lid + j * 32;
            int k = wbase + sl;
            v[j] = (sl < WPC) && (k < KK);
            if (!v[j]) k = wbase < KK ? wbase : (KK - 1);
            kc[j] = k;
            int yy = k / FWW, xx = k - yy * FWW;
            const float* p = pbase + k;
            // all 5 channel loads issued here (tx/ty prefetched)
            txr[j] = p[0];
            tyr[j] = p[KK];
            float tw = p[2*KK], th = p[3*KK], tc = p[4*KK];
            float ew = __expf(tw), eh = __expf(th);
            float conf = sigmoidf_(tc);
            pw[j] = c_aw[a] * ew;
            ph[j] = c_ah[a] * eh;
            float pa = pw[j] * ph[j];
            pa12[j] = 4.0f * (3.0f * pa);
            c2[j] = conf * conf;
            // conservative corners: center in (xx, xx+1) x (yy, yy+1)
            cxlo = fminf(cxlo, SQ7 * ((float)xx       - 0.5f * pw[j]));
            cxhi = fmaxf(cxhi, SQ7 * ((float)(xx + 1) + 0.5f * pw[j]));
            cylo = fminf(cylo, SQ7 * ((float)yy       - 0.5f * ph[j]));
            cyhi = fmaxf(cyhi, SQ7 * ((float)(yy + 1) + 0.5f * ph[j]));
            pmn = fminf(pmn, pa12[j]);
            pmx = fmaxf(pmx, pa12[j]);
        }
        // warp-level butterfly reduce (gt-independent; no smem/sync)
        #pragma unroll
        for (int o = 16; o > 0; o >>= 1) {
            cxlo = fminf(cxlo, __shfl_xor_sync(0xffffffffu, cxlo, o));
            cylo = fminf(cylo, __shfl_xor_sync(0xffffffffu, cylo, o));
            cxhi = fmaxf(cxhi, __shfl_xor_sync(0xffffffffu, cxhi, o));
            cyhi = fmaxf(cyhi, __shfl_xor_sync(0xffffffffu, cyhi, o));
            pmn  = fminf(pmn,  __shfl_xor_sync(0xffffffffu, pmn,  o));
            pmx  = fmaxf(pmx,  __shfl_xor_sync(0xffffffffu, pmx,  o));
        }
    }

    // ---- gt decode (prolog, all blocks) ----
    if (tid < TT) {
        const float* g = targets + ((size_t)b * TT + tid) * 5;
        float x1 = g[0], y1 = g[1], x2 = g[2], y2 = g[3], cl = g[4];
        bool valid = (x1 + y1 + x2 + y2) > 0.0f;

        float gx1 = x1 * FWW, gy1 = y1 * FHH, gx2 = x2 * FWW, gy2 = y2 * FHH;
        float gw = gx2 - gx1, gh = gy2 - gy1;
        float ga = gw * gh;

        if (valid) {
            s_gt[tid] = make_float4(SQ7*gx1, SQ7*gy1, SQ7*gx2, SQ7*gy2);
            s_mg4[tid] = 4.0f * (-3.0f * ga);
            s_ga7[tid] = 7.0f * ga;
        } else {
            s_gt[tid] = make_float4(1e8f, 1e8f, 1e8f, 1e8f);
            s_mg4[tid] = 0.0f;   // ga12 = 0 -> always culled by area test
            s_ga7[tid] = 0.0f;
        }

        if (part == SPARTS) {
            float gcx = 0.5f * (gx1 + gx2), gcy = 0.5f * (gy1 + gy2);
            int cx = min(max((int)floorf(gcx), 0), FWW - 1);
            int cy = min(max((int)floorf(gcy), 0), FHH - 1);
            int cell = cy * FWW + cx;

            float acx = (float)cx + 0.5f, acy = (float)cy + 0.5f;
            float best = -1e30f;
            int aidx = 0;
            #pragma unroll
            for (int aa = 0; aa < AA; aa++) {
                float aw = c_aw[aa], ah = c_ah[aa];
                float ax1 = acx - 0.5f*aw, ax2 = acx + 0.5f*aw;
                float ay1 = acy - 0.5f*ah, ay2 = acy + 0.5f*ah;
                float xi1 = fmaxf(ax1, gx1), yi1 = fmaxf(ay1, gy1);
                float xi2 = fminf(ax2, gx2), yi2 = fminf(ay2, gy2);
                float inter = fmaxf(xi2 - xi1, 0.0f) * fmaxf(yi2 - yi1, 0.0f);
                float iou = inter / (aw * ah + ga - inter);
                if (iou > best) { best = iou; aidx = aa; }
            }
            s_tb[tid]   = make_float4(gcx - (float)cx, gcy - (float)cy,
                                      gw / c_aw[aidx], gh / c_ah[aidx]);
            s_cls[tid]  = (int)cl;
            s_slot[tid] = cell * AA + aidx;
            s_valid[tid] = valid ? 1 : 0;
        }
    }
    __syncthreads();   // the ONLY block sync before the final reduction

    float r0 = 0.0f, r1 = 0.0f, r2 = 0.0f, r3 = 0.0f;

    if (part < SPARTS) {
        // warp-private cull via ballot compaction (deterministic, no sync).
        // IoU >= 0.75 requires ga in [0.75pa, 4/3 pa] -> keep iff
        // 12ga in [0.749*pmn, 1.335*pmx]; plus conservative bbox overlap.
        // Culled gts provably can't reach the threshold -> flags exact.
        const float loA = 0.749f * pmn, hiA = 1.335f * pmx;
        const unsigned ltmask = (1u << lid) - 1u;
        int wcnt = 0;
        {
            // round 1: t = lid (0..31)
            float4 g = s_gt[lid];
            float ga12 = -s_mg4[lid];
            bool pred = (g.x < cxhi && g.z > cxlo && g.y < cyhi && g.w > cylo &&
                         ga12 >= loA && ga12 <= hiA);
            unsigned m = __ballot_sync(0xffffffffu, pred);
            if (pred) {
                int pos = __popc(m & ltmask);
                s_cw[wid][pos] = make_float4(g.z, g.w, -g.x, -g.y);
                s_cm[wid][pos] = s_mg4[lid];
            }
            wcnt = __popc(m);
            // round 2: t = 32 + lid (32..49)
            int t2 = 32 + lid;
            bool in2 = t2 < TT;
            float4 g2 = in2 ? s_gt[t2] : make_float4(1e8f,1e8f,1e8f,1e8f);
            float ga2 = in2 ? -s_mg4[t2] : 0.0f;
            bool pred2 = in2 && (g2.x < cxhi && g2.z > cxlo &&
                                 g2.y < cyhi && g2.w > cylo &&
                                 ga2 >= loA && ga2 <= hiA);
            unsigned m2 = __ballot_sync(0xffffffffu, pred2);
            if (pred2) {
                int pos = wcnt + __popc(m2 & ltmask);
                s_cw[wid][pos] = make_float4(g2.z, g2.w, -g2.x, -g2.y);
                s_cm[wid][pos] = s_mg4[t2];
            }
            wcnt += __popc(m2);
        }
        // sentinels (exact no-ops: u=v=0, mg=0 -> f=0 <= acc)
        if (lid < 2) {
            s_cw[wid][wcnt + lid] = make_float4(-1e8f, -1e8f, -1e8f, -1e8f);
            s_cm[wid][wcnt + lid] = 0.0f;
        }
        __syncwarp();

        float acc4[NA];
        #pragma unroll
        for (int j = 0; j < NA; j++) acc4[j] = 0.0f;

        if (wcnt > 0) {  // warp-uniform: skip corner math + loop entirely
            // ---- phase 2: exact corners (tx/ty already in registers) ----
            float nx1[NA], ny1[NA], px2[NA], py2[NA];
            #pragma unroll
            for (int j = 0; j < NA; j++) {
                float sx = sigmoidf_(txr[j]), sy = sigmoidf_(tyr[j]);
                int yy = kc[j] / FWW, xx = kc[j] - yy * FWW;
                float pcx = (float)xx + sx, pcy = (float)yy + sy;
                float pwS = SQ7 * pw[j], phS = SQ7 * ph[j];
                float px1 = fmaf(SQ7, pcx, -0.5f * pwS);
                px2[j]    = fmaf(SQ7, pcx,  0.5f * pwS);
                float py1 = fmaf(SQ7, pcy, -0.5f * phS);
                py2[j]    = fmaf(SQ7, pcy,  0.5f * phS);
                nx1[j] = -px1; ny1[j] = -py1;
            }

            const float4* cw = s_cw[wid];
            const float*  cm = s_cm[wid];
            const int cntUp = (wcnt + 1) & ~1;
            for (int i = 0; i < cntUp; i += 2) {
                float4 cA = cw[i],   cB = cw[i+1];
                float mgA = cm[i],   mgB = cm[i+1];
                #pragma unroll
                for (int j = 0; j < NA; j++) {
                    float dxA = fminf(px2[j], cA.x) + fminf(nx1[j], cA.z);
                    float dyA = fminf(py2[j], cA.y) + fminf(ny1[j], cA.w);
                    float uA = dxA + fabsf(dxA);   // = 2*max(dxA,0) exactly
                    float vA = dyA + fabsf(dyA);
                    acc4[j] = fmaxf(acc4[j], fmaf(uA, vA, mgA));
                }
                #pragma unroll
                for (int j = 0; j < NA; j++) {
                    float dxB = fminf(px2[j], cB.x) + fminf(nx1[j], cB.z);
                    float dyB = fminf(py2[j], cB.y) + fminf(ny1[j], cB.w);
                    float uB = dxB + fabsf(dxB);
                    float vB = dyB + fabsf(dyB);
                    acc4[j] = fmaxf(acc4[j], fmaf(uB, vB, mgB));
                }
            }
        }

        float posAny = 0.0f;
        #pragma unroll
        for (int j = 0; j < NA; j++) {
            if (v[j]) {
                r0 += c2[j];
                if (acc4[j] >= pa12[j]) r1 += c2[j];
                if (acc4[j] >  pa12[j]) posAny = 1.0f;
            }
        }
        r3 = posAny;
    } else {
        // -------------------- assignment part -------------------------------
        __shared__ int s_fslot[TT];
        if (tid < TT) {
            int slot = s_slot[tid];
            bool fin = (s_valid[tid] != 0);
            if (fin) {
                for (int t2 = tid + 1; t2 < TT; t2++)
                    if (s_valid[t2] && s_slot[t2] == slot) { fin = false; break; }
            }
            s_fslot[tid] = fin ? slot : -1;
        }
        __syncthreads();

        if (tid < TT && s_fslot[tid] >= 0) {
            int slot = s_fslot[tid];
            int k = slot / AA, aa = slot - k * AA;
            int yy = k / FWW, xx = k - yy * FWW;
            const float* p = ob + (size_t)(aa * CH) * KK + k;

            float nx1, ny1, px2, py2, pa3, conf, sx, sy, ew, eh, pa7;
            decode_core(p, aa, xx, yy, nx1, ny1, px2, py2, pa3,
                        conf, sx, sy, ew, eh, pa7);
            float pa12 = 4.0f * pa3;

            // exact max-IoU over ALL gts + SAME flag expression as streaming
            float bi = 0.0f, bd = 1.0f, acc4 = 0.0f;
            for (int t = 0; t < TT; t++) {
                float4 g = s_gt[t];
                float dx = fminf(px2, g.z) + fminf(nx1, -g.x);
                float dy = fminf(py2, g.w) + fminf(ny1, -g.y);
                float u = dx + fabsf(dx);
                float vv = dy + fabsf(dy);
                acc4 = fmaxf(acc4, fmaf(u, vv, s_mg4[t]));
                float ix = 0.5f * u;                 // = max(dx,0) exactly
                float iy = 0.5f * vv;
                float inter = ix * iy;               // scaled (=7*inter)
                float den = pa7 + s_ga7[t] - inter;
                bool win = (inter * bd > bi * den);
                bi = win ? inter : bi;
                bd = win ? den : bd;
            }
            float miou = bi / bd;

            float4 tb = s_tb[tid];
            float d0 = sx - tb.x, d1 = sy - tb.y;
            float d2 = ew - tb.z, d3 = eh - tb.w;
            float asg = 0.5f * (d0*d0 + d1*d1 + d2*d2 + d3*d3);
            float di = OBJ_SCALE * conf - OBJ_SCALE * miou;
            asg += 0.5f * di * di;
            float lmax = -1e30f;
            #pragma unroll
            for (int c = 0; c < NCLS; c++) lmax = fmaxf(lmax, p[(5 + c) * KK]);
            float se = 0.0f;
            #pragma unroll
            for (int c = 0; c < NCLS; c++) se += __expf(p[(5 + c) * KK] - lmax);
            asg += (lmax + __logf(se)) - p[(5 + s_cls[tid]) * KK];

            r2 = asg;
            float cc = conf * conf;
            r0 = -cc;
            if (acc4 >= pa12) r1 = -cc;
        }
    }

    // ---- block reduction ----
    #pragma unroll
    for (int o = 16; o > 0; o >>= 1) {
        r0 += __shfl_down_sync(0xffffffffu, r0, o);
        r1 += __shfl_down_sync(0xffffffffu, r1, o);
        r2 += __shfl_down_sync(0xffffffffu, r2, o);
        r3 += __shfl_down_sync(0xffffffffu, r3, o);
    }
    __shared__ float rA[NW], rBs[NW], rG[NW], rP[NW];
    if (lid == 0) { rA[wid] = r0; rBs[wid] = r1; rG[wid] = r2; rP[wid] = r3; }
    __syncthreads();

    __shared__ int s_last;
    if (tid == 0) {
        float a0 = 0, b0 = 0, g0 = 0, p0 = 0;
        #pragma unroll
        for (int i = 0; i < NW; i++) {
            a0 += rA[i]; b0 += rBs[i]; g0 += rG[i]; p0 += rP[i];
        }
        g_part[b][part] = make_float4(a0, b0, g0, p0);
        __threadfence();
        unsigned done = atomicAdd(&g_done, 1u);
        s_last = (done == (unsigned)(BB * NPARTS - 1)) ? 1 : 0;
    }
    __syncthreads();

    // ---- last block: global combine (deterministic order) ----
    if (s_last) {
        __shared__ float red[64];
        if (tid < 64) {
            float accl = 0.0f;
            for (int bb = tid; bb < BB; bb += 64) {
                float sA = 0, sB = 0, sG = 0, sP = 0;
                #pragma unroll
                for (int p = 0; p < NPARTS; p++) {
                    float4 vv = g_part[bb][p];
                    sA += vv.x; sB += vv.y; sG += vv.z; sP += vv.w;
                }
                bool pos = sP > 0.0f;
                accl += 0.5f * (sA - (pos ? sB : 0.0f)) + sG;
            }
            red[tid] = accl;
        }
        __syncthreads();
        #pragma unroll
        for (int s = 32; s > 0; s >>= 1) {
            if (tid < s) red[tid] += red[tid + s];
            __syncthreads();
        }
        if (tid == 0) {
            out[0] = red[0] / (float)BB;
            g_done = 0;  // reset for next graph replay
        }
    }
}

// ---------------------------------------------------------------------------
extern "C" void kernel_launch(void* const* d_in, const int* in_sizes, int n_in,
                              void* d_out, int out_size) {
    const float* outputs = (const float*)d_in[0];
    const float* targets = (const float*)d_in[1];
    if (n_in >= 2 && in_sizes[0] < in_sizes[1]) {
        outputs = (const float*)d_in[1];
        targets = (const float*)d_in[0];
    }
    float* out = (float*)d_out;

    dim3 grid(BB, NPARTS);
    mainKernel<<<grid, THR>>>(outputs, targets, out);
}

// round 15
// speedup vs baseline: 4.0237x; 1.1376x over previous
#include <cuda_runtime.h>
#include <cuda_bf16.h>

// Problem constants
#define BB 128
#define FHH 26
#define FWW 26
#define TT 50
#define AA 5
#define NCLS 20
#define KK (FHH*FWW)          // 676
#define KA (KK*AA)            // 3380
#define CH (5+NCLS)           // 25
#define OBJ_SCALE 5.0f

#define SPARTS AA             // 5 streaming parts (one per anchor type)
#define NPARTS (SPARTS + 1)   // + assignment part
#define THR 192
#define NW (THR/32)           // 6 warps
#define WPC 113               // cells per warp (6*113 = 678 >= 676)
#define NA 4                  // slots per lane (32*4 = 128 >= 113)
#define SQ7 2.6457513110645906f

__constant__ float c_aw[AA] = {1.3221f, 3.19275f, 5.05587f, 9.47112f, 11.2364f};
__constant__ float c_ah[AA] = {1.73145f, 4.00944f, 8.09892f, 4.84053f, 10.0071f};

// Scratch
__device__ float4 g_part[BB][NPARTS];
__device__ unsigned g_done = 0;

__device__ __forceinline__ float sigmoidf_(float x) {
    return 1.0f / (1.0f + __expf(-x));
}

// gt decode — the ONE expression sequence used by both streaming warps and
// the assignment block so all derived values are bitwise identical.
__device__ __forceinline__ void gt_decode(
    const float* __restrict__ g,   // 5 floats: x1 y1 x2 y2 cls
    float4& gt, float& mg4, float& ga7)
{
    float x1 = g[0], y1 = g[1], x2 = g[2], y2 = g[3];
    bool valid = (x1 + y1 + x2 + y2) > 0.0f;
    float gx1 = x1 * FWW, gy1 = y1 * FHH, gx2 = x2 * FWW, gy2 = y2 * FHH;
    float gw = gx2 - gx1, gh = gy2 - gy1;
    float ga = gw * gh;
    if (valid) {
        gt  = make_float4(SQ7*gx1, SQ7*gy1, SQ7*gx2, SQ7*gy2);
        mg4 = 4.0f * (-3.0f * ga);
        ga7 = 7.0f * ga;
    } else {
        gt  = make_float4(1e8f, 1e8f, 1e8f, 1e8f);
        mg4 = 0.0f;    // ga12 = 0 -> always culled by area test
        ga7 = 0.0f;
    }
}

// Full anchor decode for the assignment path — expression-identical to the
// streaming phase1+phase2 sequence.
__device__ __forceinline__ void decode_core(
    const float* __restrict__ p, int a, int xx, int yy,
    float& nx1, float& ny1, float& px2, float& py2,
    float& pa3, float& conf, float& sx, float& sy,
    float& ew, float& eh, float& pa7)
{
    float tx = p[0], ty = p[KK], tw = p[2*KK], th = p[3*KK], tc = p[4*KK];
    sx = sigmoidf_(tx); sy = sigmoidf_(ty);
    ew = __expf(tw);    eh = __expf(th);
    conf = sigmoidf_(tc);
    float pw = c_aw[a] * ew, ph = c_ah[a] * eh;
    float pa = pw * ph;
    pa3 = 3.0f * pa;
    float pcx = (float)xx + sx, pcy = (float)yy + sy;
    float pwS = SQ7 * pw, phS = SQ7 * ph;
    float px1 = fmaf(SQ7, pcx, -0.5f * pwS);
    px2       = fmaf(SQ7, pcx,  0.5f * pwS);
    float py1 = fmaf(SQ7, pcy, -0.5f * phS);
    py2       = fmaf(SQ7, pcy,  0.5f * phS);
    nx1 = -px1; ny1 = -py1;
    pa7 = pwS * phS;
}

// ---------------------------------------------------------------------------
// grid (B, 6): part < 5 -> streaming over all 676 cells of anchor `part`
// (6 warps x 113 contiguous cells each); part 5 -> assignment.
// Streaming blocks have NO gt prolog and NO __syncthreads before the final
// reduction: each warp loads+decodes the 50 gts itself (targets are 128KB,
// L2-hot) and culls with its own ballot into a warp-private list.
// ---------------------------------------------------------------------------
__global__ __launch_bounds__(THR)
void mainKernel(const float* __restrict__ outputs,
                const float* __restrict__ targets,
                float* __restrict__ out) {
    const int b    = blockIdx.x;
    const int part = blockIdx.y;
    const int tid  = threadIdx.x;
    const int wid  = tid >> 5;
    const int lid  = tid & 31;

    // warp-private compact lists (+2 sentinel slots each)
    __shared__ float4 s_cw[NW][TT+2];    // (X2, Y2, -X1, -Y1)
    __shared__ float  s_cm[NW][TT+2];    // -12*ga
    // assignment-only tables
    __shared__ float4 s_gt[TT];
    __shared__ float  s_mg4[TT];
    __shared__ float  s_ga7[TT];
    __shared__ int    s_slot[TT];
    __shared__ int    s_valid[TT];
    __shared__ float4 s_tb[TT];
    __shared__ int    s_cls[TT];

    const float* ob = outputs + (size_t)b * CH * KA;
    const float* tb_base = targets + (size_t)b * TT * 5;

    float r0 = 0.0f, r1 = 0.0f, r2 = 0.0f, r3 = 0.0f;

    if (part < SPARTS) {
        // -------------------- streaming: anchor type a --------------------
        const int a = part;
        const float* pbase = ob + (size_t)(a * CH) * KK;
        const int wbase = wid * WPC;     // warp-contiguous 113-cell range

        // ---- phase 1: load tw/th/tc; conservative geometry (warp-local) ----
        int   kc[NA];
        bool  v[NA];
        float pw[NA], ph[NA], pa12[NA], c2[NA];
        float cxlo = 1e30f, cylo = 1e30f, cxhi = -1e30f, cyhi = -1e30f;
        float pmn = 1e30f, pmx = -1e30f;
        #pragma unroll
        for (int j = 0; j < NA; j++) {
            int sl = lid + j * 32;
            int k = wbase + sl;
            v[j] = (sl < WPC) && (k < KK);
            if (!v[j]) k = wbase < KK ? wbase : (KK - 1);
            kc[j] = k;
            int yy = k / FWW, xx = k - yy * FWW;
            const float* p = pbase + k;
            float tw = p[2*KK], th = p[3*KK], tc = p[4*KK];
            float ew = __expf(tw), eh = __expf(th);
            float conf = sigmoidf_(tc);
            pw[j] = c_aw[a] * ew;
            ph[j] = c_ah[a] * eh;
            float pa = pw[j] * ph[j];
            pa12[j] = 4.0f * (3.0f * pa);
            c2[j] = conf * conf;
            // conservative corners: center in (xx, xx+1) x (yy, yy+1)
            cxlo = fminf(cxlo, SQ7 * ((float)xx       - 0.5f * pw[j]));
            cxhi = fmaxf(cxhi, SQ7 * ((float)(xx + 1) + 0.5f * pw[j]));
            cylo = fminf(cylo, SQ7 * ((float)yy       - 0.5f * ph[j]));
            cyhi = fmaxf(cyhi, SQ7 * ((float)(yy + 1) + 0.5f * ph[j]));
            pmn = fminf(pmn, pa12[j]);
            pmx = fmaxf(pmx, pa12[j]);
        }

        // each lane loads + decodes its own gts (no smem, no block sync);
        // these loads overlap the anchor loads in the same MLP window.
        float4 gtA; float mgA_, ga7A_;
        gt_decode(tb_base + lid * 5, gtA, mgA_, ga7A_);
        int t2 = 32 + lid;
        float4 gtB = make_float4(1e8f, 1e8f, 1e8f, 1e8f);
        float mgB_ = 0.0f, ga7B_;
        if (t2 < TT) gt_decode(tb_base + t2 * 5, gtB, mgB_, ga7B_);

        // warp-level butterfly reduce (all lanes get results; no smem/sync)
        #pragma unroll
        for (int o = 16; o > 0; o >>= 1) {
            cxlo = fminf(cxlo, __shfl_xor_sync(0xffffffffu, cxlo, o));
            cylo = fminf(cylo, __shfl_xor_sync(0xffffffffu, cylo, o));
            cxhi = fmaxf(cxhi, __shfl_xor_sync(0xffffffffu, cxhi, o));
            cyhi = fmaxf(cyhi, __shfl_xor_sync(0xffffffffu, cyhi, o));
            pmn  = fminf(pmn,  __shfl_xor_sync(0xffffffffu, pmn,  o));
            pmx  = fmaxf(pmx,  __shfl_xor_sync(0xffffffffu, pmx,  o));
        }

        // warp-private cull via ballot compaction (deterministic, no sync).
        // IoU >= 0.75 requires ga in [0.75pa, 4/3 pa] -> keep iff
        // 12ga in [0.749*pmn, 1.335*pmx]; plus conservative bbox overlap.
        // Culled gts provably can't reach the threshold -> flags exact.
        const float loA = 0.749f * pmn, hiA = 1.335f * pmx;
        const unsigned ltmask = (1u << lid) - 1u;
        int wcnt = 0;
        {
            float ga12 = -mgA_;
            bool pred = (gtA.x < cxhi && gtA.z > cxlo &&
                         gtA.y < cyhi && gtA.w > cylo &&
                         ga12 >= loA && ga12 <= hiA);
            unsigned m = __ballot_sync(0xffffffffu, pred);
            if (pred) {
                int pos = __popc(m & ltmask);
                s_cw[wid][pos] = make_float4(gtA.z, gtA.w, -gtA.x, -gtA.y);
                s_cm[wid][pos] = mgA_;
            }
            wcnt = __popc(m);
            float ga2 = -mgB_;
            bool pred2 = (t2 < TT) && (gtB.x < cxhi && gtB.z > cxlo &&
                                       gtB.y < cyhi && gtB.w > cylo &&
                                       ga2 >= loA && ga2 <= hiA);
            unsigned m2 = __ballot_sync(0xffffffffu, pred2);
            if (pred2) {
                int pos = wcnt + __popc(m2 & ltmask);
                s_cw[wid][pos] = make_float4(gtB.z, gtB.w, -gtB.x, -gtB.y);
                s_cm[wid][pos] = mgB_;
            }
            wcnt += __popc(m2);
        }
        // sentinels (exact no-ops: u=v=0, mg=0 -> f=0 <= acc)
        if (lid < 2) {
            s_cw[wid][wcnt + lid] = make_float4(-1e8f, -1e8f, -1e8f, -1e8f);
            s_cm[wid][wcnt + lid] = 0.0f;
        }
        __syncwarp();

        float acc4[NA];
        #pragma unroll
        for (int j = 0; j < NA; j++) acc4[j] = 0.0f;

        if (wcnt > 0) {  // warp-uniform: skip phase 2 + loop entirely
            // ---- phase 2: load tx/ty, exact corners ----
            float nx1[NA], ny1[NA], px2[NA], py2[NA];
            #pragma unroll
            for (int j = 0; j < NA; j++) {
                const float* p = pbase + kc[j];
                float tx = p[0], ty = p[KK];
                float sx = sigmoidf_(tx), sy = sigmoidf_(ty);
                int yy = kc[j] / FWW, xx = kc[j] - yy * FWW;
                float pcx = (float)xx + sx, pcy = (float)yy + sy;
                float pwS = SQ7 * pw[j], phS = SQ7 * ph[j];
                float px1 = fmaf(SQ7, pcx, -0.5f * pwS);
                px2[j]    = fmaf(SQ7, pcx,  0.5f * pwS);
                float py1 = fmaf(SQ7, pcy, -0.5f * phS);
                py2[j]    = fmaf(SQ7, pcy,  0.5f * phS);
                nx1[j] = -px1; ny1[j] = -py1;
            }

            const float4* cw = s_cw[wid];
            const float*  cm = s_cm[wid];
            const int cntUp = (wcnt + 1) & ~1;
            for (int i = 0; i < cntUp; i += 2) {
                float4 cA = cw[i],   cB = cw[i+1];
                float mgA = cm[i],   mgB = cm[i+1];
                #pragma unroll
                for (int j = 0; j < NA; j++) {
                    float dxA = fminf(px2[j], cA.x) + fminf(nx1[j], cA.z);
                    float dyA = fminf(py2[j], cA.y) + fminf(ny1[j], cA.w);
                    float uA = dxA + fabsf(dxA);   // = 2*max(dxA,0) exactly
                    float vA = dyA + fabsf(dyA);
                    acc4[j] = fmaxf(acc4[j], fmaf(uA, vA, mgA));
                }
                #pragma unroll
                for (int j = 0; j < NA; j++) {
                    float dxB = fminf(px2[j], cB.x) + fminf(nx1[j], cB.z);
                    float dyB = fminf(py2[j], cB.y) + fminf(ny1[j], cB.w);
                    float uB = dxB + fabsf(dxB);
                    float vB = dyB + fabsf(dyB);
                    acc4[j] = fmaxf(acc4[j], fmaf(uB, vB, mgB));
                }
            }
        }

        float posAny = 0.0f;
        #pragma unroll
        for (int j = 0; j < NA; j++) {
            if (v[j]) {
                r0 += c2[j];
                if (acc4[j] >= pa12[j]) r1 += c2[j];
                if (acc4[j] >  pa12[j]) posAny = 1.0f;
            }
        }
        r3 = posAny;
    } else {
        // -------------------- assignment part (block-synced prolog) ---------
        if (tid < TT) {
            const float* g = tb_base + tid * 5;
            float4 gt; float mg4, ga7;
            gt_decode(g, gt, mg4, ga7);
            s_gt[tid]  = gt;
            s_mg4[tid] = mg4;
            s_ga7[tid] = ga7;

            float x1 = g[0], y1 = g[1], x2 = g[2], y2 = g[3], cl = g[4];
            bool valid = (x1 + y1 + x2 + y2) > 0.0f;
            float gx1 = x1 * FWW, gy1 = y1 * FHH;
            float gx2 = x2 * FWW, gy2 = y2 * FHH;
            float gw = gx2 - gx1, gh = gy2 - gy1;
            float ga = gw * gh;
            float gcx = 0.5f * (gx1 + gx2), gcy = 0.5f * (gy1 + gy2);
            int cx = min(max((int)floorf(gcx), 0), FWW - 1);
            int cy = min(max((int)floorf(gcy), 0), FHH - 1);
            int cell = cy * FWW + cx;

            float acx = (float)cx + 0.5f, acy = (float)cy + 0.5f;
            float best = -1e30f;
            int aidx = 0;
            #pragma unroll
            for (int aa = 0; aa < AA; aa++) {
                float aw = c_aw[aa], ah = c_ah[aa];
                float ax1 = acx - 0.5f*aw, ax2 = acx + 0.5f*aw;
                float ay1 = acy - 0.5f*ah, ay2 = acy + 0.5f*ah;
                float xi1 = fmaxf(ax1, gx1), yi1 = fmaxf(ay1, gy1);
                float xi2 = fminf(ax2, gx2), yi2 = fminf(ay2, gy2);
                float inter = fmaxf(xi2 - xi1, 0.0f) * fmaxf(yi2 - yi1, 0.0f);
                float iou = inter / (aw * ah + ga - inter);
                if (iou > best) { best = iou; aidx = aa; }
            }
            s_tb[tid]   = make_float4(gcx - (float)cx, gcy - (float)cy,
                                      gw / c_aw[aidx], gh / c_ah[aidx]);
            s_cls[tid]  = (int)cl;
            s_slot[tid] = cell * AA + aidx;
            s_valid[tid] = valid ? 1 : 0;
        }
        __syncthreads();

        __shared__ int s_fslot[TT];
        if (tid < TT) {
            int slot = s_slot[tid];
            bool fin = (s_valid[tid] != 0);
            if (fin) {
                for (int t2 = tid + 1; t2 < TT; t2++)
                    if (s_valid[t2] && s_slot[t2] == slot) { fin = false; break; }
            }
            s_fslot[tid] = fin ? slot : -1;
        }
        __syncthreads();

        if (tid < TT && s_fslot[tid] >= 0) {
            int slot = s_fslot[tid];
            int k = slot / AA, aa = slot - k * AA;
            int yy = k / FWW, xx = k - yy * FWW;
            const float* p = ob + (size_t)(aa * CH) * KK + k;

            float nx1, ny1, px2, py2, pa3, conf, sx, sy, ew, eh, pa7;
            decode_core(p, aa, xx, yy, nx1, ny1, px2, py2, pa3,
                        conf, sx, sy, ew, eh, pa7);
            float pa12 = 4.0f * pa3;

            // exact max-IoU over ALL gts + SAME flag expression as streaming
            float bi = 0.0f, bd = 1.0f, acc4 = 0.0f;
            for (int t = 0; t < TT; t++) {
                float4 g = s_gt[t];
                float dx = fminf(px2, g.z) + fminf(nx1, -g.x);
                float dy = fminf(py2, g.w) + fminf(ny1, -g.y);
                float u = dx + fabsf(dx);
                float vv = dy + fabsf(dy);
                acc4 = fmaxf(acc4, fmaf(u, vv, s_mg4[t]));
                float ix = 0.5f * u;                 // = max(dx,0) exactly
                float iy = 0.5f * vv;
                float inter = ix * iy;               // scaled (=7*inter)
                float den = pa7 + s_ga7[t] - inter;
                bool win = (inter * bd > bi * den);
                bi = win ? inter : bi;
                bd = win ? den : bd;
            }
            float miou = bi / bd;

            float4 tb = s_tb[tid];
            float d0 = sx - tb.x, d1 = sy - tb.y;
            float d2 = ew - tb.z, d3 = eh - tb.w;
            float asg = 0.5f * (d0*d0 + d1*d1 + d2*d2 + d3*d3);
            float di = OBJ_SCALE * conf - OBJ_SCALE * miou;
            asg += 0.5f * di * di;
            float lmax = -1e30f;
            #pragma unroll
            for (int c = 0; c < NCLS; c++) lmax = fmaxf(lmax, p[(5 + c) * KK]);
            float se = 0.0f;
            #pragma unroll
            for (int c = 0; c < NCLS; c++) se += __expf(p[(5 + c) * KK] - lmax);
            asg += (lmax + __logf(se)) - p[(5 + s_cls[tid]) * KK];

            r2 = asg;
            float cc = conf * conf;
            r0 = -cc;
            if (acc4 >= pa12) r1 = -cc;
        }
    }

    // ---- block reduction ----
    #pragma unroll
    for (int o = 16; o > 0; o >>= 1) {
        r0 += __shfl_down_sync(0xffffffffu, r0, o);
        r1 += __shfl_down_sync(0xffffffffu, r1, o);
        r2 += __shfl_down_sync(0xffffffffu, r2, o);
        r3 += __shfl_down_sync(0xffffffffu, r3, o);
    }
    __shared__ float rA[NW], rBs[NW], rG[NW], rP[NW];
    if (lid == 0) { rA[wid] = r0; rBs[wid] = r1; rG[wid] = r2; rP[wid] = r3; }
    __syncthreads();

    __shared__ int s_last;
    if (tid == 0) {
        float a0 = 0, b0 = 0, g0 = 0, p0 = 0;
        #pragma unroll
        for (int i = 0; i < NW; i++) {
            a0 += rA[i]; b0 += rBs[i]; g0 += rG[i]; p0 += rP[i];
        }
        g_part[b][part] = make_float4(a0, b0, g0, p0);
        __threadfence();
        unsigned done = atomicAdd(&g_done, 1u);
        s_last = (done == (unsigned)(BB * NPARTS - 1)) ? 1 : 0;
    }
    __syncthreads();

    // ---- last block: global combine (deterministic order) ----
    if (s_last) {
        __shared__ float red[64];
        if (tid < 64) {
            float accl = 0.0f;
            for (int bb = tid; bb < BB; bb += 64) {
                float sA = 0, sB = 0, sG = 0, sP = 0;
                #pragma unroll
                for (int p = 0; p < NPARTS; p++) {
                    float4 vv = g_part[bb][p];
                    sA += vv.x; sB += vv.y; sG += vv.z; sP += vv.w;
                }
                bool pos = sP > 0.0f;
                accl += 0.5f * (sA - (pos ? sB : 0.0f)) + sG;
            }
            red[tid] = accl;
        }
        __syncthreads();
        #pragma unroll
        for (int s = 32; s > 0; s >>= 1) {
            if (tid < s) red[tid] += red[tid + s];
            __syncthreads();
        }
        if (tid == 0) {
            out[0] = red[0] / (float)BB;
            g_done = 0;  // reset for next graph replay
        }
    }
}

// ---------------------------------------------------------------------------
extern "C" void kernel_launch(void* const* d_in, const int* in_sizes, int n_in,
                              void* d_out, int out_size) {
    const float* outputs = (const float*)d_in[0];
    const float* targets = (const float*)d_in[1];
    if (n_in >= 2 && in_sizes[0] < in_sizes[1]) {
        outputs = (const float*)d_in[1];
        targets = (const float*)d_in[0];
    }
    float* out = (float*)d_out;

    dim3 grid(BB, NPARTS);
    mainKernel<<<grid, THR>>>(outputs, targets, out);
}